// round 15
// baseline (speedup 1.0000x reference)
#include <cuda_runtime.h>
#include <cuda_bf16.h>
#include <cstdint>

typedef unsigned long long u64;
typedef unsigned int u32;
typedef unsigned char u8;

#define TOKENS 2048
#define IN_DIM 1024
#define OUT_DIM 512
#define RANK 32
#define NTG 32
#define NCELL 128
#define NTILE 16
#define NOCB 8
#define NSLOT 192
#define NFRAG 12

__device__ __align__(16) float g_z[TOKENS * RANK];
__device__ __align__(16) u32   g_zsp[TOKENS * 32];          // [tok][16 hi,16 lo]
__device__ __align__(16) u8    g_win[TOKENS * NTG];
__device__ __align__(16) u32   g_wt[(size_t)NCELL * 2 * OUT_DIM * 16];
__device__ __align__(16) float g_bsum[(size_t)TOKENS * OUT_DIM];
__device__ __align__(16) u8    g_perm[NTILE * NTG * NSLOT];
__device__ u8  g_fragc[NTILE * NTG * NFRAG];
__device__ int g_nfrag[NTILE * NTG];

__device__ __forceinline__ u32 pkbf(float a, float b) {
    __nv_bfloat16 ha = __float2bfloat16(a), hb = __float2bfloat16(b);
    return (u32)__bfloat16_as_ushort(ha) | ((u32)__bfloat16_as_ushort(hb) << 16);
}
#define MMA(d0,d1,d2,d3,a0,a1,a2,a3,b0,b1) \
    asm volatile("mma.sync.aligned.m16n8k16.row.col.f32.bf16.bf16.f32 " \
        "{%0,%1,%2,%3},{%4,%5,%6,%7},{%8,%9},{%0,%1,%2,%3};" \
        : "+f"(d0),"+f"(d1),"+f"(d2),"+f"(d3) \
        : "r"(a0),"r"(a1),"r"(a2),"r"(a3),"r"(b0),"r"(b1))
#define LDSM4(r0,r1,r2,r3,addr) \
    asm volatile("ldmatrix.sync.aligned.m8n8.x4.shared.b16 {%0,%1,%2,%3}, [%4];" \
        : "=r"(r0),"=r"(r1),"=r"(r2),"=r"(r3) : "r"(addr))

// ===== Kernel 1: kRoute (verified) + bf16 hi/lo split of z ==================
#define SMEM_ROUTE 50816
__global__ __launch_bounds__(256) void kRoute(
    const float* __restrict__ x, const float* __restrict__ proj_w,
    const float* __restrict__ router_w, const float* __restrict__ router_b) {
    extern __shared__ __align__(16) unsigned char smr[];
    float* xs   = (float*)smr;
    float* rw_s = (float*)(smr + 32768);
    float* rb_s = (float*)(smr + 49280);
    float* zs   = (float*)(smr + 49792);
    const int tid = threadIdx.x, tok0 = blockIdx.x * 8;
    {
        const float4* xg = (const float4*)(x + (size_t)tok0 * IN_DIM);
        float4* xs4 = (float4*)xs;
#pragma unroll
        for (int i = 0; i < 8; i++) xs4[tid + 256 * i] = xg[tid + 256 * i];
    }
#pragma unroll
    for (int e = tid; e < 1024; e += 256) {
        const float4 v = ((const float4*)router_w)[e];
        const int tg = e >> 5, w4 = e & 31;
        float* d = &rw_s[tg * 129 + (w4 >> 3) * 32 + (w4 & 7) * 4];
        d[0] = v.x; d[1] = v.y; d[2] = v.z; d[3] = v.w;
    }
    if (tid < 128) rb_s[tid] = router_b[tid];
    __syncthreads();

    const int w = tid >> 5, lane = tid & 31;
    float acc[4][8];
#pragma unroll
    for (int j = 0; j < 4; j++)
#pragma unroll
        for (int t = 0; t < 8; t++) acc[j][t] = 0.f;
    const float4* pw4 = (const float4*)(proj_w + (size_t)(w * 4) * IN_DIM) + lane;
    const float4* xs4 = (const float4*)xs + lane;
    float4 wv[4], wn[4];
#pragma unroll
    for (int j = 0; j < 4; j++) wv[j] = __ldg(pw4 + j * 256);
#pragma unroll
    for (int ci = 0; ci < 8; ci++) {
        if (ci < 7)
#pragma unroll
            for (int j = 0; j < 4; j++) wn[j] = __ldg(pw4 + j * 256 + (ci + 1) * 32);
#pragma unroll
        for (int t = 0; t < 8; t++) {
            const float4 xv = xs4[t * 256 + ci * 32];
#pragma unroll
            for (int j = 0; j < 4; j++) {
                acc[j][t] += wv[j].x * xv.x; acc[j][t] += wv[j].y * xv.y;
                acc[j][t] += wv[j].z * xv.z; acc[j][t] += wv[j].w * xv.w;
            }
        }
#pragma unroll
        for (int j = 0; j < 4; j++) wv[j] = wn[j];
    }
#pragma unroll
    for (int j = 0; j < 4; j++)
#pragma unroll
        for (int t = 0; t < 8; t++) {
            float s = acc[j][t];
#pragma unroll
            for (int off = 16; off > 0; off >>= 1)
                s += __shfl_xor_sync(0xffffffffu, s, off);
            if (lane == 0) zs[t * 32 + w * 4 + j] = s;
        }
    __syncthreads();
    if (tid < 64)
        ((float4*)(g_z + (size_t)tok0 * RANK))[tid] = ((const float4*)zs)[tid];
    if (tid < 128) {   // bf16 hi/lo split -> g_zsp
        const int t = tid >> 4, kk = tid & 15;
        const float z0 = zs[t * 32 + 2 * kk], z1 = zs[t * 32 + 2 * kk + 1];
        const __nv_bfloat16 h0 = __float2bfloat16(z0), h1 = __float2bfloat16(z1);
        g_zsp[(size_t)(tok0 + t) * 32 + kk] =
            (u32)__bfloat16_as_ushort(h0) | ((u32)__bfloat16_as_ushort(h1) << 16);
        g_zsp[(size_t)(tok0 + t) * 32 + 16 + kk] =
            pkbf(z0 - __bfloat162float(h0), z1 - __bfloat162float(h1));
    }
    {
        const int t = tid >> 5, tg = tid & 31;
        float s[4];
#pragma unroll
        for (int k = 0; k < 4; k++) s[k] = rb_s[tg * 4 + k];
#pragma unroll 8
        for (int r = 0; r < RANK; r++) {
            const float zr = zs[t * 32 + r];
#pragma unroll
            for (int k = 0; k < 4; k++) s[k] += zr * rw_s[tg * 129 + k * 32 + r];
        }
        int best = 0; float bv = s[0];
#pragma unroll
        for (int k = 1; k < 4; k++)
            if (s[k] < bv) { bv = s[k]; best = k; }
        g_win[(size_t)(tok0 + t) * NTG + tg] = (u8)best;
    }
}

// ===== Kernel 2: weight transpose to col-major k-pair tiles =================
// g_wt[cell][split][n 512][kk 16] u32 = {bf(W[2kk][n]), bf(W[2kk+1][n])}
__global__ __launch_bounds__(256) void kPrepW(const float* __restrict__ aw) {
    const int cell = blockIdx.x, tid = threadIdx.x;
#pragma unroll
    for (int h = 0; h < 2; h++) {
        const int n = tid + h * 256;
        u32 hi[16], lo[16];
#pragma unroll
        for (int kk = 0; kk < 16; kk++) {
            const float v0 = __ldg(&aw[((size_t)cell * RANK + 2 * kk) * OUT_DIM + n]);
            const float v1 = __ldg(&aw[((size_t)cell * RANK + 2 * kk + 1) * OUT_DIM + n]);
            const __nv_bfloat16 h0 = __float2bfloat16(v0), h1 = __float2bfloat16(v1);
            hi[kk] = (u32)__bfloat16_as_ushort(h0) | ((u32)__bfloat16_as_ushort(h1) << 16);
            lo[kk] = pkbf(v0 - __bfloat162float(h0), v1 - __bfloat162float(h1));
        }
        u32* dh = g_wt + (((size_t)cell * 2 + 0) * OUT_DIM + n) * 16;
        u32* dl = g_wt + (((size_t)cell * 2 + 1) * OUT_DIM + n) * 16;
#pragma unroll
        for (int q = 0; q < 4; q++) {
            ((uint4*)dh)[q] = make_uint4(hi[4*q], hi[4*q+1], hi[4*q+2], hi[4*q+3]);
            ((uint4*)dl)[q] = make_uint4(lo[4*q], lo[4*q+1], lo[4*q+2], lo[4*q+3]);
        }
    }
}

// ===== Kernel 3: grid (16, 9): y==8 -> per-tile sort; y<8 -> bias sums ======
#define SMEM_SB 37120
__global__ __launch_bounds__(256) void kSB(const float* __restrict__ ab) {
    extern __shared__ __align__(16) unsigned char sms[];
    const int tid = threadIdx.x, bx = blockIdx.x;
    const int tile0 = bx * 128;

    if (blockIdx.y == 8) {   // ---- sort path ----
        u8* win_t = sms;                      // [32][132]
        u8* ord   = sms + 4224;               // [32][192]
        if (tid < 128) {
            const u32* wp = (const u32*)(g_win + (size_t)(tile0 + tid) * NTG);
#pragma unroll
            for (int q = 0; q < 8; q++) {
                const u32 v = wp[q];
                win_t[(q*4+0)*132 + tid] = (u8)(v);
                win_t[(q*4+1)*132 + tid] = (u8)(v >> 8);
                win_t[(q*4+2)*132 + tid] = (u8)(v >> 16);
                win_t[(q*4+3)*132 + tid] = (u8)(v >> 24);
            }
        }
        __syncthreads();
        if (tid < NTG) {
            const int tg = tid;
            int cnt[4] = {0,0,0,0};
            for (int t = 0; t < 128; t++) cnt[win_t[tg*132 + t]]++;
            int o[5]; o[0] = 0;
#pragma unroll
            for (int c = 0; c < 4; c++) o[c+1] = o[c] + ((cnt[c] + 15) & ~15);
            int pos[4];
#pragma unroll
            for (int c = 0; c < 4; c++) pos[c] = o[c];
            for (int t = 0; t < 128; t++)
                ord[tg*192 + pos[win_t[tg*132 + t]]++] = (u8)t;
#pragma unroll
            for (int c = 0; c < 4; c++)
                for (int i = cnt[c]; i < o[c+1] - o[c]; i++)
                    ord[tg*192 + o[c] + i] = 0xFF;
            for (int i = o[4]; i < NSLOT; i++) ord[tg*192 + i] = 0xFF;
            const int nf = o[4] >> 4;
            g_nfrag[bx * NTG + tg] = nf;
            for (int f = 0; f < NFRAG; f++) {
                int cell = 3;
#pragma unroll
                for (int c = 0; c < 3; c++)
                    if (f * 16 < o[c+1]) { cell = c; break; }
                // FIX (R14 bug): store GLOBAL cell id (tg*4 + k), not local k
                g_fragc[(bx * NTG + tg) * NFRAG + f] = (u8)(tg * 4 + cell);
            }
            u8* pg = g_perm + (size_t)(bx * NTG + tg) * NSLOT;
            for (int i = 0; i < NSLOT; i++) pg[i] = ord[tg*192 + i];
        }
    } else {                 // ---- bias-sum path ----
        float* bias_s = (float*)sms;          // [128 cells][64]
        u8*    win_s  = sms + 32768;          // [128][32]
        const int oc = blockIdx.y * 64;
        for (int e = tid; e < 2048; e += 256) {
            const int c = e >> 4, o4 = e & 15;
            ((float4*)&bias_s[c * 64])[o4] =
                __ldg((const float4*)(ab + (size_t)c * OUT_DIM + oc) + o4);
        }
        if (tid < 128) {
            const uint4* ws = (const uint4*)(g_win + (size_t)(tile0 + tid) * NTG);
            ((uint4*)(win_s + tid * 32))[0] = ws[0];
            ((uint4*)(win_s + tid * 32))[1] = ws[1];
        }
        __syncthreads();
        const int tok = tid >> 1, half = tid & 1;
        float s[32];
#pragma unroll
        for (int i = 0; i < 32; i++) s[i] = 0.f;
        for (int tg = 0; tg < 32; tg++) {
            const int cell = tg * 4 + win_s[tok * 32 + tg];
            const float* br = bias_s + cell * 64 + half * 32;
#pragma unroll
            for (int i = 0; i < 32; i++) s[i] += br[i];
        }
        float* op = g_bsum + (size_t)(tile0 + tok) * OUT_DIM + oc + half * 32;
#pragma unroll
        for (int i = 0; i < 8; i++)
            ((float4*)op)[i] = make_float4(s[4*i], s[4*i+1], s[4*i+2], s[4*i+3]);
    }
}

// ===== Kernel 4: mma.sync apply =============================================
// grid (16 tiles, 8 oc64) x 256 thr.  Warp w owns output cols w*8..w*8+7
// (no cross-warp acc races, no RMW barriers).  Per tg: permuted z rows ->
// ldmatrix A frags; B via L1/L2-cached LDG from g_wt; 3 split-combo mma chains.
#define SMEM_APPLY 76480
__global__ __launch_bounds__(256) void kApplyT(float* __restrict__ out) {
    extern __shared__ __align__(16) unsigned char sm[];
    u32*   zsp_s  = (u32*)sm;                       // [128][32]
    float* acc    = (float*)(sm + 40960);           // [128][68]
    u8*    sperm  = sm + 75776;
    u8*    fragc_s= sm + 75968;                     // [32][12]
    int*   nfrag_s= (int*)(sm + 76352);
    const u32 smb = (u32)__cvta_generic_to_shared(sm);
    const u32 phiB = smb + 16384, ploB = smb + 28672;

    const int tid = threadIdx.x, w = tid >> 5, lane = tid & 31;
    const int bx = blockIdx.x, tile0 = bx * 128;
    const int oc = blockIdx.y * 64;

    for (int e = tid; e < 1024; e += 256) {
        const int tok = e >> 3, q = e & 7;
        ((uint4*)&zsp_s[tok * 32])[q] =
            __ldg((const uint4*)(g_zsp + (size_t)(tile0 + tok) * 32) + q);
    }
    for (int e = tid; e < 2048; e += 256) {
        const int tok = e >> 4, o4 = e & 15;
        const float4 v = __ldg(
            (const float4*)(g_bsum + (size_t)(tile0 + tok) * OUT_DIM + oc) + o4);
        *(float4*)&acc[tok * 68 + o4 * 4] = v;
    }
    if (tid < 32) nfrag_s[tid] = g_nfrag[bx * NTG + tid];
    for (int e = tid; e < NTG * NFRAG; e += 256)
        fragc_s[e] = g_fragc[bx * NTG * NFRAG + e];
    __syncthreads();

    for (int tg = 0; tg < NTG; tg++) {
        __syncthreads();   // prior P/sperm reads done before overwrite
        const u8* pg = g_perm + (size_t)(bx * NTG + tg) * NSLOT;
        for (int e = tid; e < NSLOT; e += 256) sperm[e] = pg[e];
        for (int e = tid; e < NSLOT * 4; e += 256) {
            const int slot = e >> 2, q = e & 3;
            const u8 tok = pg[slot];
            if (tok != 0xFF) {
                const uint4 vh = ((const uint4*)&zsp_s[tok * 32])[q];
                const uint4 vl = ((const uint4*)&zsp_s[tok * 32])[q + 4];
                *(uint4*)(sm + 16384 + slot * 64 + q * 16) = vh;
                *(uint4*)(sm + 28672 + slot * 64 + q * 16) = vl;
            }
        }
        __syncthreads();

        const int nf = nfrag_s[tg];
        const int nn = oc + w * 8 + (lane >> 2);
        const u32 rowoff = (u32)((lane & 15) * 64 + (lane >> 4) * 16);
        for (int f = 0; f < nf; f++) {
            const int cell = fragc_s[tg * NFRAG + f];     // GLOBAL cell id
            const u32* wbh = g_wt + (((size_t)cell * 2 + 0) * OUT_DIM + nn) * 16 + (lane & 3);
            const u32* wbl = wbh + (size_t)OUT_DIM * 16;
            const u32 bh0 = __ldg(wbh), bh1 = __ldg(wbh + 4);
            const u32 bh2 = __ldg(wbh + 8), bh3 = __ldg(wbh + 12);
            const u32 bl0 = __ldg(wbl), bl1 = __ldg(wbl + 4);
            const u32 bl2 = __ldg(wbl + 8), bl3 = __ldg(wbl + 12);
            const u32 pa = (u32)(f * 16 * 64) + rowoff;
            u32 ah0,ah1,ah2,ah3, ah4,ah5,ah6,ah7, al0,al1,al2,al3, al4,al5,al6,al7;
            LDSM4(ah0,ah1,ah2,ah3, phiB + pa);
            LDSM4(ah4,ah5,ah6,ah7, phiB + pa + 32);
            LDSM4(al0,al1,al2,al3, ploB + pa);
            LDSM4(al4,al5,al6,al7, ploB + pa + 32);
            float da0=0,da1=0,da2=0,da3=0, db0=0,db1=0,db2=0,db3=0,
                  dc0=0,dc1=0,dc2=0,dc3=0;
            MMA(da0,da1,da2,da3, ah0,ah1,ah2,ah3, bh0,bh1);
            MMA(db0,db1,db2,db3, ah0,ah1,ah2,ah3, bl0,bl1);
            MMA(dc0,dc1,dc2,dc3, al0,al1,al2,al3, bh0,bh1);
            MMA(da0,da1,da2,da3, ah4,ah5,ah6,ah7, bh2,bh3);
            MMA(db0,db1,db2,db3, ah4,ah5,ah6,ah7, bl2,bl3);
            MMA(dc0,dc1,dc2,dc3, al4,al5,al6,al7, bh2,bh3);
            const int col = w * 8 + (lane & 3) * 2;
            const u8 s0 = sperm[f * 16 + (lane >> 2)];
            const u8 s1 = sperm[f * 16 + 8 + (lane >> 2)];
            if (s0 != 0xFF) {
                float* p = &acc[(int)s0 * 68 + col];
                p[0] += da0 + db0 + dc0;
                p[1] += da1 + db1 + dc1;
            }
            if (s1 != 0xFF) {
                float* p = &acc[(int)s1 * 68 + col];
                p[0] += da2 + db2 + dc2;
                p[1] += da3 + db3 + dc3;
            }
        }
    }
    __syncthreads();

    const float S = 0.17677669529663687f;   // 1/sqrt(32)
    for (int e = tid; e < 2048; e += 256) {
        const int tok = e >> 4, o4 = e & 15;
        float4 v = *(const float4*)&acc[tok * 68 + o4 * 4];
        v.x *= S; v.y *= S; v.z *= S; v.w *= S;
        ((float4*)(out + (size_t)(tile0 + tok) * OUT_DIM + oc))[o4] = v;
    }
}

// =============================================================================
extern "C" void kernel_launch(void* const* d_in, const int* in_sizes, int n_in,
                              void* d_out, int out_size) {
    const float* x  = (const float*)d_in[0];
    const float* pw = (const float*)d_in[1];
    const float* rw = (const float*)d_in[2];
    const float* rb = (const float*)d_in[3];
    const float* aw = (const float*)d_in[4];
    const float* ab = (const float*)d_in[5];
    float* out = (float*)d_out;

    cudaFuncSetAttribute(kRoute, cudaFuncAttributeMaxDynamicSharedMemorySize,
                         SMEM_ROUTE);
    cudaFuncSetAttribute(kSB, cudaFuncAttributeMaxDynamicSharedMemorySize,
                         SMEM_SB);
    cudaFuncSetAttribute(kApplyT, cudaFuncAttributeMaxDynamicSharedMemorySize,
                         SMEM_APPLY);

    kRoute<<<TOKENS / 8, 256, SMEM_ROUTE>>>(x, pw, rw, rb);
    kPrepW<<<NCELL, 256>>>(aw);
    kSB<<<dim3(NTILE, 9), 256, SMEM_SB>>>(ab);
    kApplyT<<<dim3(NTILE, NOCB), 256, SMEM_APPLY>>>(out);
}

// round 16
// speedup vs baseline: 1.6426x; 1.6426x over previous
#include <cuda_runtime.h>
#include <cuda_bf16.h>
#include <cstdint>

typedef unsigned long long u64;
typedef unsigned int u32;
typedef unsigned char u8;

#define TOKENS 2048
#define IN_DIM 1024
#define OUT_DIM 512
#define RANK 32
#define NTG 32
#define NCELL 128
#define NTILE 16
#define NOCB 8
#define NSLOT 192
#define NFRAG 12

__device__ __align__(16) float g_z[TOKENS * RANK];
__device__ __align__(16) u32   g_zsp[TOKENS * 32];          // [tok][16 hi,16 lo]
__device__ __align__(16) u8    g_win[TOKENS * NTG];
__device__ __align__(16) u32   g_wt[(size_t)NCELL * 2 * OUT_DIM * 16];
__device__ __align__(16) float g_bsum[(size_t)TOKENS * OUT_DIM];
__device__ __align__(16) u8    g_perm[NTILE * NTG * NSLOT];
__device__ __align__(16) u8    g_pa[(size_t)NTILE * NTG * 2 * NSLOT * 64];
__device__ u8  g_fragc[NTILE * NTG * NFRAG];                // LOCAL cell 0..3
__device__ int g_nfrag[NTILE * NTG];

__device__ __forceinline__ u32 pkbf(float a, float b) {
    __nv_bfloat16 ha = __float2bfloat16(a), hb = __float2bfloat16(b);
    return (u32)__bfloat16_as_ushort(ha) | ((u32)__bfloat16_as_ushort(hb) << 16);
}
#define MMA(d0,d1,d2,d3,a0,a1,a2,a3,b0,b1) \
    asm volatile("mma.sync.aligned.m16n8k16.row.col.f32.bf16.bf16.f32 " \
        "{%0,%1,%2,%3},{%4,%5,%6,%7},{%8,%9},{%0,%1,%2,%3};" \
        : "+f"(d0),"+f"(d1),"+f"(d2),"+f"(d3) \
        : "r"(a0),"r"(a1),"r"(a2),"r"(a3),"r"(b0),"r"(b1))
#define LDSM4(r0,r1,r2,r3,addr) \
    asm volatile("ldmatrix.sync.aligned.m8n8.x4.shared.b16 {%0,%1,%2,%3}, [%4];" \
        : "=r"(r0),"=r"(r1),"=r"(r2),"=r"(r3) : "r"(addr))
#define LDSM2(r0,r1,addr) \
    asm volatile("ldmatrix.sync.aligned.m8n8.x2.shared.b16 {%0,%1}, [%2];" \
        : "=r"(r0),"=r"(r1) : "r"(addr))
#define CPA16(dst, src) \
    asm volatile("cp.async.ca.shared.global [%0], [%1], 16;" :: "r"(dst), "l"(src))

// ===== Kernel 1: kRoute (verified) + bf16 hi/lo split of z ==================
#define SMEM_ROUTE 50816
__global__ __launch_bounds__(256) void kRoute(
    const float* __restrict__ x, const float* __restrict__ proj_w,
    const float* __restrict__ router_w, const float* __restrict__ router_b) {
    extern __shared__ __align__(16) unsigned char smr[];
    float* xs   = (float*)smr;
    float* rw_s = (float*)(smr + 32768);
    float* rb_s = (float*)(smr + 49280);
    float* zs   = (float*)(smr + 49792);
    const int tid = threadIdx.x, tok0 = blockIdx.x * 8;
    {
        const float4* xg = (const float4*)(x + (size_t)tok0 * IN_DIM);
        float4* xs4 = (float4*)xs;
#pragma unroll
        for (int i = 0; i < 8; i++) xs4[tid + 256 * i] = xg[tid + 256 * i];
    }
#pragma unroll
    for (int e = tid; e < 1024; e += 256) {
        const float4 v = ((const float4*)router_w)[e];
        const int tg = e >> 5, w4 = e & 31;
        float* d = &rw_s[tg * 129 + (w4 >> 3) * 32 + (w4 & 7) * 4];
        d[0] = v.x; d[1] = v.y; d[2] = v.z; d[3] = v.w;
    }
    if (tid < 128) rb_s[tid] = router_b[tid];
    __syncthreads();

    const int w = tid >> 5, lane = tid & 31;
    float acc[4][8];
#pragma unroll
    for (int j = 0; j < 4; j++)
#pragma unroll
        for (int t = 0; t < 8; t++) acc[j][t] = 0.f;
    const float4* pw4 = (const float4*)(proj_w + (size_t)(w * 4) * IN_DIM) + lane;
    const float4* xs4 = (const float4*)xs + lane;
    float4 wv[4], wn[4];
#pragma unroll
    for (int j = 0; j < 4; j++) wv[j] = __ldg(pw4 + j * 256);
#pragma unroll
    for (int ci = 0; ci < 8; ci++) {
        if (ci < 7)
#pragma unroll
            for (int j = 0; j < 4; j++) wn[j] = __ldg(pw4 + j * 256 + (ci + 1) * 32);
#pragma unroll
        for (int t = 0; t < 8; t++) {
            const float4 xv = xs4[t * 256 + ci * 32];
#pragma unroll
            for (int j = 0; j < 4; j++) {
                acc[j][t] += wv[j].x * xv.x; acc[j][t] += wv[j].y * xv.y;
                acc[j][t] += wv[j].z * xv.z; acc[j][t] += wv[j].w * xv.w;
            }
        }
#pragma unroll
        for (int j = 0; j < 4; j++) wv[j] = wn[j];
    }
#pragma unroll
    for (int j = 0; j < 4; j++)
#pragma unroll
        for (int t = 0; t < 8; t++) {
            float s = acc[j][t];
#pragma unroll
            for (int off = 16; off > 0; off >>= 1)
                s += __shfl_xor_sync(0xffffffffu, s, off);
            if (lane == 0) zs[t * 32 + w * 4 + j] = s;
        }
    __syncthreads();
    if (tid < 64)
        ((float4*)(g_z + (size_t)tok0 * RANK))[tid] = ((const float4*)zs)[tid];
    if (tid < 128) {
        const int t = tid >> 4, kk = tid & 15;
        const float z0 = zs[t * 32 + 2 * kk], z1 = zs[t * 32 + 2 * kk + 1];
        const __nv_bfloat16 h0 = __float2bfloat16(z0), h1 = __float2bfloat16(z1);
        g_zsp[(size_t)(tok0 + t) * 32 + kk] =
            (u32)__bfloat16_as_ushort(h0) | ((u32)__bfloat16_as_ushort(h1) << 16);
        g_zsp[(size_t)(tok0 + t) * 32 + 16 + kk] =
            pkbf(z0 - __bfloat162float(h0), z1 - __bfloat162float(h1));
    }
    {
        const int t = tid >> 5, tg = tid & 31;
        float s[4];
#pragma unroll
        for (int k = 0; k < 4; k++) s[k] = rb_s[tg * 4 + k];
#pragma unroll 8
        for (int r = 0; r < RANK; r++) {
            const float zr = zs[t * 32 + r];
#pragma unroll
            for (int k = 0; k < 4; k++) s[k] += zr * rw_s[tg * 129 + k * 32 + r];
        }
        int best = 0; float bv = s[0];
#pragma unroll
        for (int k = 1; k < 4; k++)
            if (s[k] < bv) { bv = s[k]; best = k; }
        g_win[(size_t)(tok0 + t) * NTG + tg] = (u8)best;
    }
}

// ===== Kernel 2: weight split/transpose (unchanged, verified) ===============
__global__ __launch_bounds__(256) void kPrepW(const float* __restrict__ aw) {
    const int cell = blockIdx.x, tid = threadIdx.x;
#pragma unroll
    for (int h = 0; h < 2; h++) {
        const int n = tid + h * 256;
        u32 hi[16], lo[16];
#pragma unroll
        for (int kk = 0; kk < 16; kk++) {
            const float v0 = __ldg(&aw[((size_t)cell * RANK + 2 * kk) * OUT_DIM + n]);
            const float v1 = __ldg(&aw[((size_t)cell * RANK + 2 * kk + 1) * OUT_DIM + n]);
            const __nv_bfloat16 h0 = __float2bfloat16(v0), h1 = __float2bfloat16(v1);
            hi[kk] = (u32)__bfloat16_as_ushort(h0) | ((u32)__bfloat16_as_ushort(h1) << 16);
            lo[kk] = pkbf(v0 - __bfloat162float(h0), v1 - __bfloat162float(h1));
        }
        u32* dh = g_wt + (((size_t)cell * 2 + 0) * OUT_DIM + n) * 16;
        u32* dl = g_wt + (((size_t)cell * 2 + 1) * OUT_DIM + n) * 16;
#pragma unroll
        for (int q = 0; q < 4; q++) {
            ((uint4*)dh)[q] = make_uint4(hi[4*q], hi[4*q+1], hi[4*q+2], hi[4*q+3]);
            ((uint4*)dl)[q] = make_uint4(lo[4*q], lo[4*q+1], lo[4*q+2], lo[4*q+3]);
        }
    }
}

// ===== Kernel 3: grid (16, 9): y==8 -> sort + permuted-A build; else bias ===
#define SMEM_SB 37120
__global__ __launch_bounds__(256) void kSB(const float* __restrict__ ab) {
    extern __shared__ __align__(16) unsigned char sms[];
    const int tid = threadIdx.x, bx = blockIdx.x;
    const int tile0 = bx * 128;

    if (blockIdx.y == 8) {
        u8* win_t = sms;                      // [32][132]
        u8* ord   = sms + 4224;               // [32][192]
        if (tid < 128) {
            const u32* wp = (const u32*)(g_win + (size_t)(tile0 + tid) * NTG);
#pragma unroll
            for (int q = 0; q < 8; q++) {
                const u32 v = wp[q];
                win_t[(q*4+0)*132 + tid] = (u8)(v);
                win_t[(q*4+1)*132 + tid] = (u8)(v >> 8);
                win_t[(q*4+2)*132 + tid] = (u8)(v >> 16);
                win_t[(q*4+3)*132 + tid] = (u8)(v >> 24);
            }
        }
        __syncthreads();
        if (tid < NTG) {
            const int tg = tid;
            int cnt[4] = {0,0,0,0};
            for (int t = 0; t < 128; t++) cnt[win_t[tg*132 + t]]++;
            int o[5]; o[0] = 0;
#pragma unroll
            for (int c = 0; c < 4; c++) o[c+1] = o[c] + ((cnt[c] + 15) & ~15);
            int pos[4];
#pragma unroll
            for (int c = 0; c < 4; c++) pos[c] = o[c];
            for (int t = 0; t < 128; t++)
                ord[tg*192 + pos[win_t[tg*132 + t]]++] = (u8)t;
#pragma unroll
            for (int c = 0; c < 4; c++)
                for (int i = cnt[c]; i < o[c+1] - o[c]; i++)
                    ord[tg*192 + o[c] + i] = 0xFF;
            for (int i = o[4]; i < NSLOT; i++) ord[tg*192 + i] = 0xFF;
            g_nfrag[bx * NTG + tg] = o[4] >> 4;
            for (int f = 0; f < NFRAG; f++) {
                int cell = 3;
#pragma unroll
                for (int c = 0; c < 3; c++)
                    if (f * 16 < o[c+1]) { cell = c; break; }
                g_fragc[(bx * NTG + tg) * NFRAG + f] = (u8)cell;   // LOCAL
            }
            u8* pg = g_perm + (size_t)(bx * NTG + tg) * NSLOT;
            for (int i = 0; i < NSLOT; i++) pg[i] = ord[tg*192 + i];
        }
        __syncthreads();
        // permuted A tiles: [tile,tg][split][slot][64B]
        for (int e = tid; e < NTG * 2 * NSLOT * 4; e += 256) {
            const int tg = e / 1536, rem = e - tg * 1536;
            const int s = rem / 768, rem2 = rem - s * 768;
            const int slot = rem2 >> 2, q = rem2 & 3;
            const u8 tok = ord[tg * 192 + slot];
            uint4 v = make_uint4(0, 0, 0, 0);
            if (tok != 0xFF)
                v = *(const uint4*)(g_zsp + (size_t)(tile0 + tok) * 32 + s * 16 + q * 4);
            *(uint4*)(g_pa + ((size_t)((bx * 32 + tg) * 2 + s)) * 12288 +
                      slot * 64 + q * 16) = v;
        }
    } else {
        float* bias_s = (float*)sms;          // [128 cells][64]
        u8*    win_s  = sms + 32768;          // [128][32]
        const int oc = blockIdx.y * 64;
        for (int e = tid; e < 2048; e += 256) {
            const int c = e >> 4, o4 = e & 15;
            ((float4*)&bias_s[c * 64])[o4] =
                __ldg((const float4*)(ab + (size_t)c * OUT_DIM + oc) + o4);
        }
        if (tid < 128) {
            const uint4* ws = (const uint4*)(g_win + (size_t)(tile0 + tid) * NTG);
            ((uint4*)(win_s + tid * 32))[0] = ws[0];
            ((uint4*)(win_s + tid * 32))[1] = ws[1];
        }
        __syncthreads();
        const int tok = tid >> 1, half = tid & 1;
        float s[32];
#pragma unroll
        for (int i = 0; i < 32; i++) s[i] = 0.f;
        for (int tg = 0; tg < 32; tg++) {
            const int cell = tg * 4 + win_s[tok * 32 + tg];
            const float* br = bias_s + cell * 64 + half * 32;
#pragma unroll
            for (int i = 0; i < 32; i++) s[i] += br[i];
        }
        float* op = g_bsum + (size_t)(tile0 + tok) * OUT_DIM + oc + half * 32;
#pragma unroll
        for (int i = 0; i < 8; i++)
            ((float4*)op)[i] = make_float4(s[4*i], s[4*i+1], s[4*i+2], s[4*i+3]);
    }
}

// ===== Kernel 4: mma.sync apply v2 ==========================================
// grid (16 tiles, 8 oc64) x 256 thr.  Per tg (cp.async double-buffered A+B,
// 80B-padded rows -> conflict-free ldmatrix): warp w takes fragments w, w+8;
// sweeps all 8 n-tiles (A ldsm once per fragment).  Concurrent fragments of a
// tg touch disjoint tokens -> scatter race-free; 2 barriers/tg.
// smem: Abuf 2x(2x192x80)=61440 | Bbuf 2x(4x2x64x80)=81920 @61440 |
//       acc[128][68] @143360 | sperm 2x192 @178176 | fragc @178560 | nfrag @178944
#define SMEM_APPLY 179072
__global__ __launch_bounds__(256) void kApplyT(float* __restrict__ out) {
    extern __shared__ __align__(16) unsigned char sm[];
    float* acc     = (float*)(sm + 143360);
    u8*    sperm   = sm + 178176;
    u8*    fragc_s = sm + 178560;
    int*   nfrag_s = (int*)(sm + 178944);
    const u32 smb = (u32)__cvta_generic_to_shared(sm);

    const int tid = threadIdx.x, w = tid >> 5, lane = tid & 31;
    const int bx = blockIdx.x, tile0 = bx * 128;
    const int oc = blockIdx.y * 64;

    for (int e = tid; e < 2048; e += 256) {
        const int tok = e >> 4, o4 = e & 15;
        const float4 v = __ldg(
            (const float4*)(g_bsum + (size_t)(tile0 + tok) * OUT_DIM + oc) + o4);
        *(float4*)&acc[tok * 68 + o4 * 4] = v;
    }
    if (tid < 32) nfrag_s[tid] = g_nfrag[bx * NTG + tid];
    for (int e = tid; e < NTG * NFRAG; e += 256)
        fragc_s[e] = g_fragc[bx * NTG * NFRAG + e];

    // ---- staging helper ----
    auto stage = [&](int tg, int buf) {
        for (int e = tid; e < 1536; e += 256) {            // A: 2 splits
            const int s = e / 768, rem = e - s * 768;
            const int slot = rem >> 2, q = rem & 3;
            const u8* src = g_pa + ((size_t)((bx * 32 + tg) * 2 + s)) * 12288 +
                            slot * 64 + q * 16;
            CPA16(smb + (u32)(buf * 30720 + s * 15360 + slot * 80 + q * 16), src);
        }
        for (int e = tid; e < 2048; e += 256) {            // B: 4 cells x 2 splits
            const int c = e >> 9, rem = e & 511;
            const int s = rem >> 8, rem2 = rem & 255;
            const int n = rem2 >> 2, q = rem2 & 3;
            const u8* src = (const u8*)g_wt +
                (((size_t)(tg * 4 + c) * 2 + s) * 512 + oc + n) * 64 + q * 16;
            CPA16(smb + (u32)(61440 + buf * 40960 + c * 10240 + s * 5120 +
                              n * 80 + q * 16), src);
        }
        if (tid < 12) {                                    // sperm
            const u8* src = g_perm + (size_t)(bx * 32 + tg) * NSLOT + tid * 16;
            CPA16(smb + (u32)(178176 + buf * 192 + tid * 16), src);
        }
        asm volatile("cp.async.commit_group;" ::: "memory");
    };

    stage(0, 0);
    for (int tg = 0; tg < NTG; tg++) {
        const int buf = tg & 1;
        if (tg + 1 < NTG) {
            stage(tg + 1, buf ^ 1);
            asm volatile("cp.async.wait_group 1;" ::: "memory");
        } else {
            asm volatile("cp.async.wait_group 0;" ::: "memory");
        }
        __syncthreads();

        const int nf = nfrag_s[tg];
        const u32 Abase = smb + (u32)(buf * 30720);
        const u32 Bbase = smb + (u32)(61440 + buf * 40960);
        const u8* sp = sperm + buf * 192;
        const u32 rowoff = (u32)((lane & 15) * 80 + (lane >> 4) * 16);
        const u32 bro = (u32)((lane & 7) * 80 + ((lane >> 3) & 1) * 16);

        for (int fi = w; fi < nf; fi += 8) {
            const int c = fragc_s[tg * NFRAG + fi];
            const u32 fb = (u32)(fi * 16 * 80);
            u32 ah0,ah1,ah2,ah3, ah4,ah5,ah6,ah7;
            u32 al0,al1,al2,al3, al4,al5,al6,al7;
            LDSM4(ah0,ah1,ah2,ah3, Abase + fb + rowoff);
            LDSM4(ah4,ah5,ah6,ah7, Abase + fb + rowoff + 32);
            LDSM4(al0,al1,al2,al3, Abase + 15360 + fb + rowoff);
            LDSM4(al4,al5,al6,al7, Abase + 15360 + fb + rowoff + 32);
            const u32 Bc = Bbase + (u32)(c * 10240);
            const u8 s0 = sp[fi * 16 + (lane >> 2)];
            const u8 s1 = sp[fi * 16 + 8 + (lane >> 2)];
#pragma unroll
            for (int nt = 0; nt < 8; nt++) {
                const u32 Bn = Bc + (u32)(nt * 640);
                u32 bh0,bh1,bh2,bh3, bl0,bl1,bl2,bl3;
                LDSM2(bh0,bh1, Bn + bro);
                LDSM2(bh2,bh3, Bn + bro + 32);
                LDSM2(bl0,bl1, Bn + 5120 + bro);
                LDSM2(bl2,bl3, Bn + 5120 + bro + 32);
                float d0 = 0.f, d1 = 0.f, d2 = 0.f, d3 = 0.f;
                MMA(d0,d1,d2,d3, ah0,ah1,ah2,ah3, bh0,bh1);
                MMA(d0,d1,d2,d3, ah4,ah5,ah6,ah7, bh2,bh3);
                MMA(d0,d1,d2,d3, ah0,ah1,ah2,ah3, bl0,bl1);
                MMA(d0,d1,d2,d3, ah4,ah5,ah6,ah7, bl2,bl3);
                MMA(d0,d1,d2,d3, al0,al1,al2,al3, bh0,bh1);
                MMA(d0,d1,d2,d3, al4,al5,al6,al7, bh2,bh3);
                const int col = nt * 8 + (lane & 3) * 2;
                if (s0 != 0xFF) {
                    float* p = &acc[(int)s0 * 68 + col];
                    p[0] += d0; p[1] += d1;
                }
                if (s1 != 0xFF) {
                    float* p = &acc[(int)s1 * 68 + col];
                    p[0] += d2; p[1] += d3;
                }
            }
        }
        __syncthreads();
    }

    const float S = 0.17677669529663687f;   // 1/sqrt(32)
    for (int e = tid; e < 2048; e += 256) {
        const int tok = e >> 4, o4 = e & 15;
        float4 v = *(const float4*)&acc[tok * 68 + o4 * 4];
        v.x *= S; v.y *= S; v.z *= S; v.w *= S;
        ((float4*)(out + (size_t)(tile0 + tok) * OUT_DIM + oc))[o4] = v;
    }
}

// =============================================================================
extern "C" void kernel_launch(void* const* d_in, const int* in_sizes, int n_in,
                              void* d_out, int out_size) {
    const float* x  = (const float*)d_in[0];
    const float* pw = (const float*)d_in[1];
    const float* rw = (const float*)d_in[2];
    const float* rb = (const float*)d_in[3];
    const float* aw = (const float*)d_in[4];
    const float* ab = (const float*)d_in[5];
    float* out = (float*)d_out;

    cudaFuncSetAttribute(kRoute, cudaFuncAttributeMaxDynamicSharedMemorySize,
                         SMEM_ROUTE);
    cudaFuncSetAttribute(kSB, cudaFuncAttributeMaxDynamicSharedMemorySize,
                         SMEM_SB);
    cudaFuncSetAttribute(kApplyT, cudaFuncAttributeMaxDynamicSharedMemorySize,
                         SMEM_APPLY);

    kRoute<<<TOKENS / 8, 256, SMEM_ROUTE>>>(x, pw, rw, rb);
    kPrepW<<<NCELL, 256>>>(aw);
    kSB<<<dim3(NTILE, 9), 256, SMEM_SB>>>(ab);
    kApplyT<<<dim3(NTILE, NOCB), 256, SMEM_APPLY>>>(out);
}

// round 17
// speedup vs baseline: 1.8137x; 1.1042x over previous
#include <cuda_runtime.h>
#include <cuda_bf16.h>
#include <cstdint>

typedef unsigned long long u64;
typedef unsigned int u32;
typedef unsigned char u8;

#define TOKENS 2048
#define IN_DIM 1024
#define OUT_DIM 512
#define RANK 32
#define NTG 32
#define NCELL 128
#define NTILE 16
#define NOCB 8
#define NSLOT 192
#define NFRAG 12

__device__ __align__(16) float g_z[TOKENS * RANK];
__device__ __align__(16) u32   g_zsp[TOKENS * 32];          // [tok][16 hi,16 lo]
__device__ __align__(16) u8    g_win[TOKENS * NTG];
__device__ __align__(16) u32   g_wt[(size_t)NCELL * 2 * OUT_DIM * 16];
__device__ __align__(16) float g_bsum[(size_t)TOKENS * OUT_DIM];
__device__ __align__(16) u8    g_perm[NTILE * NTG * NSLOT];
__device__ __align__(16) u8    g_pa[(size_t)NTILE * NTG * 2 * NSLOT * 64];
__device__ u8  g_fragc[NTILE * NTG * NFRAG];                // LOCAL cell 0..3
__device__ int g_nfrag[NTILE * NTG];

__device__ __forceinline__ u32 pkbf(float a, float b) {
    __nv_bfloat16 ha = __float2bfloat16(a), hb = __float2bfloat16(b);
    return (u32)__bfloat16_as_ushort(ha) | ((u32)__bfloat16_as_ushort(hb) << 16);
}
#define MMA(d0,d1,d2,d3,a0,a1,a2,a3,b0,b1) \
    asm volatile("mma.sync.aligned.m16n8k16.row.col.f32.bf16.bf16.f32 " \
        "{%0,%1,%2,%3},{%4,%5,%6,%7},{%8,%9},{%0,%1,%2,%3};" \
        : "+f"(d0),"+f"(d1),"+f"(d2),"+f"(d3) \
        : "r"(a0),"r"(a1),"r"(a2),"r"(a3),"r"(b0),"r"(b1))
#define LDSM4(r0,r1,r2,r3,addr) \
    asm volatile("ldmatrix.sync.aligned.m8n8.x4.shared.b16 {%0,%1,%2,%3}, [%4];" \
        : "=r"(r0),"=r"(r1),"=r"(r2),"=r"(r3) : "r"(addr))
#define LDSM2(r0,r1,addr) \
    asm volatile("ldmatrix.sync.aligned.m8n8.x2.shared.b16 {%0,%1}, [%2];" \
        : "=r"(r0),"=r"(r1) : "r"(addr))
#define CPA16(dst, src) \
    asm volatile("cp.async.ca.shared.global [%0], [%1], 16;" :: "r"(dst), "l"(src))

// ===== Kernel 1: kRoute (verified) + bf16 hi/lo split of z ==================
#define SMEM_ROUTE 50816
__global__ __launch_bounds__(256) void kRoute(
    const float* __restrict__ x, const float* __restrict__ proj_w,
    const float* __restrict__ router_w, const float* __restrict__ router_b) {
    extern __shared__ __align__(16) unsigned char smr[];
    float* xs   = (float*)smr;
    float* rw_s = (float*)(smr + 32768);
    float* rb_s = (float*)(smr + 49280);
    float* zs   = (float*)(smr + 49792);
    const int tid = threadIdx.x, tok0 = blockIdx.x * 8;
    {
        const float4* xg = (const float4*)(x + (size_t)tok0 * IN_DIM);
        float4* xs4 = (float4*)xs;
#pragma unroll
        for (int i = 0; i < 8; i++) xs4[tid + 256 * i] = xg[tid + 256 * i];
    }
#pragma unroll
    for (int e = tid; e < 1024; e += 256) {
        const float4 v = ((const float4*)router_w)[e];
        const int tg = e >> 5, w4 = e & 31;
        float* d = &rw_s[tg * 129 + (w4 >> 3) * 32 + (w4 & 7) * 4];
        d[0] = v.x; d[1] = v.y; d[2] = v.z; d[3] = v.w;
    }
    if (tid < 128) rb_s[tid] = router_b[tid];
    __syncthreads();

    const int w = tid >> 5, lane = tid & 31;
    float acc[4][8];
#pragma unroll
    for (int j = 0; j < 4; j++)
#pragma unroll
        for (int t = 0; t < 8; t++) acc[j][t] = 0.f;
    const float4* pw4 = (const float4*)(proj_w + (size_t)(w * 4) * IN_DIM) + lane;
    const float4* xs4 = (const float4*)xs + lane;
    float4 wv[4], wn[4];
#pragma unroll
    for (int j = 0; j < 4; j++) wv[j] = __ldg(pw4 + j * 256);
#pragma unroll
    for (int ci = 0; ci < 8; ci++) {
        if (ci < 7)
#pragma unroll
            for (int j = 0; j < 4; j++) wn[j] = __ldg(pw4 + j * 256 + (ci + 1) * 32);
#pragma unroll
        for (int t = 0; t < 8; t++) {
            const float4 xv = xs4[t * 256 + ci * 32];
#pragma unroll
            for (int j = 0; j < 4; j++) {
                acc[j][t] += wv[j].x * xv.x; acc[j][t] += wv[j].y * xv.y;
                acc[j][t] += wv[j].z * xv.z; acc[j][t] += wv[j].w * xv.w;
            }
        }
#pragma unroll
        for (int j = 0; j < 4; j++) wv[j] = wn[j];
    }
#pragma unroll
    for (int j = 0; j < 4; j++)
#pragma unroll
        for (int t = 0; t < 8; t++) {
            float s = acc[j][t];
#pragma unroll
            for (int off = 16; off > 0; off >>= 1)
                s += __shfl_xor_sync(0xffffffffu, s, off);
            if (lane == 0) zs[t * 32 + w * 4 + j] = s;
        }
    __syncthreads();
    if (tid < 64)
        ((float4*)(g_z + (size_t)tok0 * RANK))[tid] = ((const float4*)zs)[tid];
    if (tid < 128) {
        const int t = tid >> 4, kk = tid & 15;
        const float z0 = zs[t * 32 + 2 * kk], z1 = zs[t * 32 + 2 * kk + 1];
        const __nv_bfloat16 h0 = __float2bfloat16(z0), h1 = __float2bfloat16(z1);
        g_zsp[(size_t)(tok0 + t) * 32 + kk] =
            (u32)__bfloat16_as_ushort(h0) | ((u32)__bfloat16_as_ushort(h1) << 16);
        g_zsp[(size_t)(tok0 + t) * 32 + 16 + kk] =
            pkbf(z0 - __bfloat162float(h0), z1 - __bfloat162float(h1));
    }
    {
        const int t = tid >> 5, tg = tid & 31;
        float s[4];
#pragma unroll
        for (int k = 0; k < 4; k++) s[k] = rb_s[tg * 4 + k];
#pragma unroll 8
        for (int r = 0; r < RANK; r++) {
            const float zr = zs[t * 32 + r];
#pragma unroll
            for (int k = 0; k < 4; k++) s[k] += zr * rw_s[tg * 129 + k * 32 + r];
        }
        int best = 0; float bv = s[0];
#pragma unroll
        for (int k = 1; k < 4; k++)
            if (s[k] < bv) { bv = s[k]; best = k; }
        g_win[(size_t)(tok0 + t) * NTG + tg] = (u8)best;
    }
}

// ===== Kernel 2: weight split/transpose (unchanged, verified) ===============
__global__ __launch_bounds__(256) void kPrepW(const float* __restrict__ aw) {
    const int cell = blockIdx.x, tid = threadIdx.x;
#pragma unroll
    for (int h = 0; h < 2; h++) {
        const int n = tid + h * 256;
        u32 hi[16], lo[16];
#pragma unroll
        for (int kk = 0; kk < 16; kk++) {
            const float v0 = __ldg(&aw[((size_t)cell * RANK + 2 * kk) * OUT_DIM + n]);
            const float v1 = __ldg(&aw[((size_t)cell * RANK + 2 * kk + 1) * OUT_DIM + n]);
            const __nv_bfloat16 h0 = __float2bfloat16(v0), h1 = __float2bfloat16(v1);
            hi[kk] = (u32)__bfloat16_as_ushort(h0) | ((u32)__bfloat16_as_ushort(h1) << 16);
            lo[kk] = pkbf(v0 - __bfloat162float(h0), v1 - __bfloat162float(h1));
        }
        u32* dh = g_wt + (((size_t)cell * 2 + 0) * OUT_DIM + n) * 16;
        u32* dl = g_wt + (((size_t)cell * 2 + 1) * OUT_DIM + n) * 16;
#pragma unroll
        for (int q = 0; q < 4; q++) {
            ((uint4*)dh)[q] = make_uint4(hi[4*q], hi[4*q+1], hi[4*q+2], hi[4*q+3]);
            ((uint4*)dl)[q] = make_uint4(lo[4*q], lo[4*q+1], lo[4*q+2], lo[4*q+3]);
        }
    }
}

// ===== Kernel 3: grid (16, 9): y==8 -> sort + permuted-A build; else bias ===
#define SMEM_SB 37120
__global__ __launch_bounds__(256) void kSB(const float* __restrict__ ab) {
    extern __shared__ __align__(16) unsigned char sms[];
    const int tid = threadIdx.x, bx = blockIdx.x;
    const int tile0 = bx * 128;

    if (blockIdx.y == 8) {
        u8* win_t = sms;                      // [32][132]
        u8* ord   = sms + 4224;               // [32][192]
        if (tid < 128) {
            const u32* wp = (const u32*)(g_win + (size_t)(tile0 + tid) * NTG);
#pragma unroll
            for (int q = 0; q < 8; q++) {
                const u32 v = wp[q];
                win_t[(q*4+0)*132 + tid] = (u8)(v);
                win_t[(q*4+1)*132 + tid] = (u8)(v >> 8);
                win_t[(q*4+2)*132 + tid] = (u8)(v >> 16);
                win_t[(q*4+3)*132 + tid] = (u8)(v >> 24);
            }
        }
        __syncthreads();
        if (tid < NTG) {
            const int tg = tid;
            int cnt[4] = {0,0,0,0};
            for (int t = 0; t < 128; t++) cnt[win_t[tg*132 + t]]++;
            int o[5]; o[0] = 0;
#pragma unroll
            for (int c = 0; c < 4; c++) o[c+1] = o[c] + ((cnt[c] + 15) & ~15);
            int pos[4];
#pragma unroll
            for (int c = 0; c < 4; c++) pos[c] = o[c];
            for (int t = 0; t < 128; t++)
                ord[tg*192 + pos[win_t[tg*132 + t]]++] = (u8)t;
#pragma unroll
            for (int c = 0; c < 4; c++)
                for (int i = cnt[c]; i < o[c+1] - o[c]; i++)
                    ord[tg*192 + o[c] + i] = 0xFF;
            for (int i = o[4]; i < NSLOT; i++) ord[tg*192 + i] = 0xFF;
            g_nfrag[bx * NTG + tg] = o[4] >> 4;
            for (int f = 0; f < NFRAG; f++) {
                int cell = 3;
#pragma unroll
                for (int c = 0; c < 3; c++)
                    if (f * 16 < o[c+1]) { cell = c; break; }
                g_fragc[(bx * NTG + tg) * NFRAG + f] = (u8)cell;   // LOCAL
            }
            u8* pg = g_perm + (size_t)(bx * NTG + tg) * NSLOT;
            for (int i = 0; i < NSLOT; i++) pg[i] = ord[tg*192 + i];
        }
        __syncthreads();
        // permuted A tiles: [tile,tg][split][slot][64B]
        for (int e = tid; e < NTG * 2 * NSLOT * 4; e += 256) {
            const int tg = e / 1536, rem = e - tg * 1536;
            const int s = rem / 768, rem2 = rem - s * 768;
            const int slot = rem2 >> 2, q = rem2 & 3;
            const u8 tok = ord[tg * 192 + slot];
            uint4 v = make_uint4(0, 0, 0, 0);
            if (tok != 0xFF)
                v = *(const uint4*)(g_zsp + (size_t)(tile0 + tok) * 32 + s * 16 + q * 4);
            *(uint4*)(g_pa + ((size_t)((bx * 32 + tg) * 2 + s)) * 12288 +
                      slot * 64 + q * 16) = v;
        }
    } else {
        float* bias_s = (float*)sms;          // [128 cells][64]
        u8*    win_s  = sms + 32768;          // [128][32]
        const int oc = blockIdx.y * 64;
        for (int e = tid; e < 2048; e += 256) {
            const int c = e >> 4, o4 = e & 15;
            ((float4*)&bias_s[c * 64])[o4] =
                __ldg((const float4*)(ab + (size_t)c * OUT_DIM + oc) + o4);
        }
        if (tid < 128) {
            const uint4* ws = (const uint4*)(g_win + (size_t)(tile0 + tid) * NTG);
            ((uint4*)(win_s + tid * 32))[0] = ws[0];
            ((uint4*)(win_s + tid * 32))[1] = ws[1];
        }
        __syncthreads();
        const int tok = tid >> 1, half = tid & 1;
        float s[32];
#pragma unroll
        for (int i = 0; i < 32; i++) s[i] = 0.f;
        for (int tg = 0; tg < 32; tg++) {
            const int cell = tg * 4 + win_s[tok * 32 + tg];
            const float* br = bias_s + cell * 64 + half * 32;
#pragma unroll
            for (int i = 0; i < 32; i++) s[i] += br[i];
        }
        float* op = g_bsum + (size_t)(tile0 + tok) * OUT_DIM + oc + half * 32;
#pragma unroll
        for (int i = 0; i < 8; i++)
            ((float4*)op)[i] = make_float4(s[4*i], s[4*i+1], s[4*i+2], s[4*i+3]);
    }
}

// ===== Kernel 4: mma.sync apply v3 -- 512 threads ===========================
// grid (16 tiles, 8 oc64) x 512 thr (16 warps).  warp w = (frag class w&7,
// n-half w>>3): fragments {w&7, (w&7)+8}, n-tiles [(w>>3)*4, +4).  Two warps
// share a fragment at disjoint columns; different fragments = disjoint tokens
// -> scatter race-free.  cp.async double-buffered A+B (80B rows), 2 barr/tg.
// smem: Abuf 2x(2x192x80)=61440 | Bbuf 2x(4x2x64x80)=81920 @61440 |
//       acc[128][68] @143360 | sperm 2x192 @178176 | fragc @178560 | nfrag @178944
#define SMEM_APPLY 179072
__global__ __launch_bounds__(512) void kApplyT(float* __restrict__ out) {
    extern __shared__ __align__(16) unsigned char sm[];
    float* acc     = (float*)(sm + 143360);
    u8*    sperm   = sm + 178176;
    u8*    fragc_s = sm + 178560;
    int*   nfrag_s = (int*)(sm + 178944);
    const u32 smb = (u32)__cvta_generic_to_shared(sm);

    const int tid = threadIdx.x, w = tid >> 5, lane = tid & 31;
    const int bx = blockIdx.x, tile0 = bx * 128;
    const int oc = blockIdx.y * 64;

    for (int e = tid; e < 2048; e += 512) {
        const int tok = e >> 4, o4 = e & 15;
        const float4 v = __ldg(
            (const float4*)(g_bsum + (size_t)(tile0 + tok) * OUT_DIM + oc) + o4);
        *(float4*)&acc[tok * 68 + o4 * 4] = v;
    }
    if (tid < 32) nfrag_s[tid] = g_nfrag[bx * NTG + tid];
    for (int e = tid; e < NTG * NFRAG; e += 512)
        fragc_s[e] = g_fragc[bx * NTG * NFRAG + e];

    // ---- staging helper ----
    auto stage = [&](int tg, int buf) {
        for (int e = tid; e < 1536; e += 512) {            // A: 2 splits
            const int s = e / 768, rem = e - s * 768;
            const int slot = rem >> 2, q = rem & 3;
            const u8* src = g_pa + ((size_t)((bx * 32 + tg) * 2 + s)) * 12288 +
                            slot * 64 + q * 16;
            CPA16(smb + (u32)(buf * 30720 + s * 15360 + slot * 80 + q * 16), src);
        }
        for (int e = tid; e < 2048; e += 512) {            // B: 4 cells x 2 splits
            const int c = e >> 9, rem = e & 511;
            const int s = rem >> 8, rem2 = rem & 255;
            const int n = rem2 >> 2, q = rem2 & 3;
            const u8* src = (const u8*)g_wt +
                (((size_t)(tg * 4 + c) * 2 + s) * 512 + oc + n) * 64 + q * 16;
            CPA16(smb + (u32)(61440 + buf * 40960 + c * 10240 + s * 5120 +
                              n * 80 + q * 16), src);
        }
        if (tid < 12) {                                    // sperm
            const u8* src = g_perm + (size_t)(bx * 32 + tg) * NSLOT + tid * 16;
            CPA16(smb + (u32)(178176 + buf * 192 + tid * 16), src);
        }
        asm volatile("cp.async.commit_group;" ::: "memory");
    };

    stage(0, 0);
    for (int tg = 0; tg < NTG; tg++) {
        const int buf = tg & 1;
        if (tg + 1 < NTG) {
            stage(tg + 1, buf ^ 1);
            asm volatile("cp.async.wait_group 1;" ::: "memory");
        } else {
            asm volatile("cp.async.wait_group 0;" ::: "memory");
        }
        __syncthreads();

        const int nf = nfrag_s[tg];
        const u32 Abase = smb + (u32)(buf * 30720);
        const u32 Bbase = smb + (u32)(61440 + buf * 40960);
        const u8* sp = sperm + buf * 192;
        const u32 rowoff = (u32)((lane & 15) * 80 + (lane >> 4) * 16);
        const u32 bro = (u32)((lane & 7) * 80 + ((lane >> 3) & 1) * 16);
        const int wg = w & 7, nt0 = (w >> 3) * 4;

        for (int fi = wg; fi < nf; fi += 8) {
            const int c = fragc_s[tg * NFRAG + fi];
            const u32 fb = (u32)(fi * 16 * 80);
            u32 ah0,ah1,ah2,ah3, ah4,ah5,ah6,ah7;
            u32 al0,al1,al2,al3, al4,al5,al6,al7;
            LDSM4(ah0,ah1,ah2,ah3, Abase + fb + rowoff);
            LDSM4(ah4,ah5,ah6,ah7, Abase + fb + rowoff + 32);
            LDSM4(al0,al1,al2,al3, Abase + 15360 + fb + rowoff);
            LDSM4(al4,al5,al6,al7, Abase + 15360 + fb + rowoff + 32);
            const u32 Bc = Bbase + (u32)(c * 10240);
            const u8 s0 = sp[fi * 16 + (lane >> 2)];
            const u8 s1 = sp[fi * 16 + 8 + (lane >> 2)];
#pragma unroll
            for (int ntq = 0; ntq < 4; ntq++) {
                const int nt = nt0 + ntq;
                const u32 Bn = Bc + (u32)(nt * 640);
                u32 bh0,bh1,bh2,bh3, bl0,bl1,bl2,bl3;
                LDSM2(bh0,bh1, Bn + bro);
                LDSM2(bh2,bh3, Bn + bro + 32);
                LDSM2(bl0,bl1, Bn + 5120 + bro);
                LDSM2(bl2,bl3, Bn + 5120 + bro + 32);
                float d0 = 0.f, d1 = 0.f, d2 = 0.f, d3 = 0.f;
                MMA(d0,d1,d2,d3, ah0,ah1,ah2,ah3, bh0,bh1);
                MMA(d0,d1,d2,d3, ah4,ah5,ah6,ah7, bh2,bh3);
                MMA(d0,d1,d2,d3, ah0,ah1,ah2,ah3, bl0,bl1);
                MMA(d0,d1,d2,d3, ah4,ah5,ah6,ah7, bl2,bl3);
                MMA(d0,d1,d2,d3, al0,al1,al2,al3, bh0,bh1);
                MMA(d0,d1,d2,d3, al4,al5,al6,al7, bh2,bh3);
                const int col = nt * 8 + (lane & 3) * 2;
                if (s0 != 0xFF) {
                    float* p = &acc[(int)s0 * 68 + col];
                    p[0] += d0; p[1] += d1;
                }
                if (s1 != 0xFF) {
                    float* p = &acc[(int)s1 * 68 + col];
                    p[0] += d2; p[1] += d3;
                }
            }
        }
        __syncthreads();
    }

    const float S = 0.17677669529663687f;   // 1/sqrt(32)
    for (int e = tid; e < 2048; e += 512) {
        const int tok = e >> 4, o4 = e & 15;
        float4 v = *(const float4*)&acc[tok * 68 + o4 * 4];
        v.x *= S; v.y *= S; v.z *= S; v.w *= S;
        ((float4*)(out + (size_t)(tile0 + tok) * OUT_DIM + oc))[o4] = v;
    }
}

// =============================================================================
extern "C" void kernel_launch(void* const* d_in, const int* in_sizes, int n_in,
                              void* d_out, int out_size) {
    const float* x  = (const float*)d_in[0];
    const float* pw = (const float*)d_in[1];
    const float* rw = (const float*)d_in[2];
    const float* rb = (const float*)d_in[3];
    const float* aw = (const float*)d_in[4];
    const float* ab = (const float*)d_in[5];
    float* out = (float*)d_out;

    cudaFuncSetAttribute(kRoute, cudaFuncAttributeMaxDynamicSharedMemorySize,
                         SMEM_ROUTE);
    cudaFuncSetAttribute(kSB, cudaFuncAttributeMaxDynamicSharedMemorySize,
                         SMEM_SB);
    cudaFuncSetAttribute(kApplyT, cudaFuncAttributeMaxDynamicSharedMemorySize,
                         SMEM_APPLY);

    kRoute<<<TOKENS / 8, 256, SMEM_ROUTE>>>(x, pw, rw, rb);
    kPrepW<<<NCELL, 256>>>(aw);
    kSB<<<dim3(NTILE, 9), 256, SMEM_SB>>>(ab);
    kApplyT<<<dim3(NTILE, NOCB), 512, SMEM_APPLY>>>(out);
}